// round 10
// baseline (speedup 1.0000x reference)
#include <cuda_runtime.h>
#include <cuda_bf16.h>
#include <mma.h>
#include <math.h>
#include <stdint.h>

using namespace nvcuda;

#define BB 8
#define TT 2048
#define EE 1024
#define MT (BB*TT)   // 16384
#define NCH 8
#define CHR (TT/NCH)

#define BM 128
#define BN 64
#define BK 16
#define SA (BM*BK)                 // 2048 bf16
#define SB (BN*BK)                 // 1024 bf16
#define STG_BYTES ((2*SA + 2*SB)*2)  // Ahi,Alo,Bhi,Blo = 12288 B per stage
#define CLD 72                     // C tile ld (fp32), padded
#define SMEM_BYTES 36864           // max(2*STG_BYTES=24576, 128*72*4=36864)

// ---------------- device-global scratch -------------------------------------
__device__ __nv_bfloat16 g_Xhi[(size_t)MT*EE],  g_Xlo[(size_t)MT*EE];
__device__ __nv_bfloat16 g_Whi[3][(size_t)EE*EE], g_Wlo[3][(size_t)EE*EE];
__device__ __nv_bfloat16 g_Qhi[(size_t)MT*EE],  g_Qlo[(size_t)MT*EE];
__device__ __nv_bfloat16 g_Khi[(size_t)MT*EE],  g_Klo[(size_t)MT*EE];
__device__ __nv_bfloat16 g_Vhi[(size_t)MT*EE],  g_Vlo[(size_t)MT*EE];
__device__ __nv_bfloat16 g_VShi[(size_t)MT*EE], g_VSlo[(size_t)MT*EE];  // V * 1/denom
__device__ float         g_S[(size_t)BB*TT*TT];
__device__ __nv_bfloat16 g_Phi[(size_t)BB*TT*TT], g_Plo[(size_t)BB*TT*TT];
__device__ float         g_pm[BB][NCH][TT], g_ps[BB][NCH][TT];
__device__ float         g_M[BB][TT], g_R[BB][TT];

__device__ __forceinline__ void split2(float v, __nv_bfloat16& h, __nv_bfloat16& l){
    h = __float2bfloat16(v);
    l = __float2bfloat16(v - __bfloat162float(h));
}

// ---------------------------------------------------------------------------
// preconvert fp32 -> bf16 hi/lo (X + Wq + Wk + Wv in one grid-stride launch)
// ---------------------------------------------------------------------------
__global__ void convert_all_kernel(const float* __restrict__ X,
                                   const float* __restrict__ Wq,
                                   const float* __restrict__ Wk,
                                   const float* __restrict__ Wv)
{
    const size_t nX = (size_t)MT*EE, nW = (size_t)EE*EE;
    const size_t total = nX + 3*nW;
    for (size_t i = (size_t)blockIdx.x*blockDim.x + threadIdx.x;
         i < total; i += (size_t)gridDim.x*blockDim.x){
        if (i < nX)             { split2(X[i],  g_Xhi[i],  g_Xlo[i]); }
        else if (i < nX + nW)   { size_t k=i-nX;      split2(Wq[k], g_Whi[0][k], g_Wlo[0][k]); }
        else if (i < nX + 2*nW) { size_t k=i-nX-nW;   split2(Wk[k], g_Whi[1][k], g_Wlo[1][k]); }
        else                    { size_t k=i-nX-2*nW; split2(Wv[k], g_Whi[2][k], g_Wlo[2][k]); }
    }
}

// ---------------------------------------------------------------------------
// WMMA fragment typedefs
// ---------------------------------------------------------------------------
typedef wmma::fragment<wmma::matrix_a, 16,16,16, __nv_bfloat16, wmma::row_major> FragA;
typedef wmma::fragment<wmma::matrix_b, 16,16,16, __nv_bfloat16, wmma::col_major> FragBc;
typedef wmma::fragment<wmma::matrix_b, 16,16,16, __nv_bfloat16, wmma::row_major> FragBr;
typedef wmma::fragment<wmma::accumulator, 16,16,16, float> FragC;

// 3-MMA split accumulate: acc += Ah*Bh + Ah*Bl + Al*Bh
#define SPLIT_MMA(acc, ah, al, bh, bl)            \
    wmma::mma_sync(acc, ah, bh, acc);             \
    wmma::mma_sync(acc, ah, bl, acc);             \
    wmma::mma_sync(acc, al, bh, acc);

// ---------------------------------------------------------------------------
// Kernel: QKV projection  C[m,n] = sum_e X[m,e]*W[n,e] + b[n]  (NT)
// grid (EE/BN=16, MT/BM=128, 3), 256 threads
// ---------------------------------------------------------------------------
__global__ void __launch_bounds__(256) proj_wmma(
    const float* __restrict__ bq, const float* __restrict__ bk, const float* __restrict__ bv)
{
    __shared__ __align__(32) unsigned char sm_raw[SMEM_BYTES];

    const int z  = blockIdx.z;
    const int m0 = blockIdx.y * BM;
    const int n0 = blockIdx.x * BN;
    const __nv_bfloat16* Wh = g_Whi[z];
    const __nv_bfloat16* Wl = g_Wlo[z];
    const float* bias = (z==0)? bq : (z==1)? bk : bv;
    __nv_bfloat16* Ohi = (z==0)? g_Qhi : (z==1)? g_Khi : g_Vhi;
    __nv_bfloat16* Olo = (z==0)? g_Qlo : (z==1)? g_Klo : g_Vlo;

    const int tid = threadIdx.x, wid = tid >> 5;
    const int wm = wid & 3, wn = wid >> 2;           // 4 x 2 warp grid
    // A loads: all 256 threads; row 0..127, col-group 0..1 (8 bf16 each)
    const int ar = tid >> 1, ac = (tid & 1) * 8;
    // B loads: threads t<128 -> hi, t>=128 -> lo; row 0..63, col-group 0..1
    const int bt = tid & 127, br = bt >> 1, bc = (bt & 1) * 8;
    const int bsel = tid >> 7;                        // 0: hi, 1: lo

    __nv_bfloat16* stg[2];
    stg[0] = (__nv_bfloat16*)sm_raw;
    stg[1] = (__nv_bfloat16*)(sm_raw + STG_BYTES);

    FragC acc[2][2];
    #pragma unroll
    for (int i = 0; i < 2; i++)
        #pragma unroll
        for (int j = 0; j < 2; j++)
            wmma::fill_fragment(acc[i][j], 0.0f);

    // prologue: stage 0
    {
        __nv_bfloat16* s = stg[0];
        *(uint4*)(s + ar*BK + ac)            = *(const uint4*)(g_Xhi + (size_t)(m0+ar)*EE + ac);
        *(uint4*)(s + SA + ar*BK + ac)       = *(const uint4*)(g_Xlo + (size_t)(m0+ar)*EE + ac);
        const __nv_bfloat16* Wsrc = bsel ? Wl : Wh;
        *(uint4*)(s + 2*SA + bsel*SB + br*BK + bc) = *(const uint4*)(Wsrc + (size_t)(n0+br)*EE + bc);
    }
    __syncthreads();

    const int NS = EE / BK;
    for (int s = 0; s < NS; s++){
        const int buf = s & 1;
        uint4 rAh, rAl, rB;
        if (s+1 < NS){
            const int k0 = (s+1)*BK;
            rAh = *(const uint4*)(g_Xhi + (size_t)(m0+ar)*EE + k0 + ac);
            rAl = *(const uint4*)(g_Xlo + (size_t)(m0+ar)*EE + k0 + ac);
            const __nv_bfloat16* Wsrc = bsel ? Wl : Wh;
            rB  = *(const uint4*)(Wsrc + (size_t)(n0+br)*EE + k0 + bc);
        }
        // compute on buf
        {
            __nv_bfloat16* sbuf = stg[buf];
            FragBc bh[2], bl[2];
            #pragma unroll
            for (int j = 0; j < 2; j++){
                wmma::load_matrix_sync(bh[j], sbuf + 2*SA      + (wn*32 + j*16)*BK, BK);
                wmma::load_matrix_sync(bl[j], sbuf + 2*SA + SB + (wn*32 + j*16)*BK, BK);
            }
            #pragma unroll
            for (int i = 0; i < 2; i++){
                FragA ah, al;
                wmma::load_matrix_sync(ah, sbuf      + (wm*32 + i*16)*BK, BK);
                wmma::load_matrix_sync(al, sbuf + SA + (wm*32 + i*16)*BK, BK);
                #pragma unroll
                for (int j = 0; j < 2; j++){ SPLIT_MMA(acc[i][j], ah, al, bh[j], bl[j]) }
            }
        }
        if (s+1 < NS){
            __nv_bfloat16* sn = stg[buf ^ 1];
            *(uint4*)(sn + ar*BK + ac)      = rAh;
            *(uint4*)(sn + SA + ar*BK + ac) = rAl;
            *(uint4*)(sn + 2*SA + bsel*SB + br*BK + bc) = rB;
        }
        __syncthreads();
    }

    // epilogue: C -> smem, bias, split-store
    float* C = (float*)sm_raw;
    #pragma unroll
    for (int i = 0; i < 2; i++)
        #pragma unroll
        for (int j = 0; j < 2; j++)
            wmma::store_matrix_sync(C + (wm*32 + i*16)*CLD + wn*32 + j*16,
                                    acc[i][j], CLD, wmma::mem_row_major);
    __syncthreads();
    for (int idx = tid; idx < BM*BN; idx += 256){
        int r = idx >> 6, c = idx & 63;
        float v = C[r*CLD + c] + bias[n0 + c];
        __nv_bfloat16 h, l; split2(v, h, l);
        Ohi[(size_t)(m0+r)*EE + n0 + c] = h;
        Olo[(size_t)(m0+r)*EE + n0 + c] = l;
    }
}

// ---------------------------------------------------------------------------
// Kernel: masked logits S[b,i,j] = Q.K (NT); j>i -> -inf; tiles with
// j0 >= i0+BM skipped. grid (TT/BN=32 (j), TT/BM=16 (i), BB)
// ---------------------------------------------------------------------------
__global__ void __launch_bounds__(256) logits_wmma()
{
    const int b  = blockIdx.z;
    const int i0 = blockIdx.y * BM;
    const int j0 = blockIdx.x * BN;
    if (j0 >= i0 + BM) return;

    __shared__ __align__(32) unsigned char sm_raw[SMEM_BYTES];

    const __nv_bfloat16* Ah0 = g_Qhi + (size_t)(b*TT + i0)*EE;
    const __nv_bfloat16* Al0 = g_Qlo + (size_t)(b*TT + i0)*EE;
    const __nv_bfloat16* Bh0 = g_Khi + (size_t)(b*TT + j0)*EE;
    const __nv_bfloat16* Bl0 = g_Klo + (size_t)(b*TT + j0)*EE;
    float* S = g_S + (size_t)b*TT*TT;

    const int tid = threadIdx.x, wid = tid >> 5;
    const int wm = wid & 3, wn = wid >> 2;
    const int ar = tid >> 1, ac = (tid & 1) * 8;
    const int bt = tid & 127, br = bt >> 1, bc = (bt & 1) * 8;
    const int bsel = tid >> 7;

    __nv_bfloat16* stg[2];
    stg[0] = (__nv_bfloat16*)sm_raw;
    stg[1] = (__nv_bfloat16*)(sm_raw + STG_BYTES);

    FragC acc[2][2];
    #pragma unroll
    for (int i = 0; i < 2; i++)
        #pragma unroll
        for (int j = 0; j < 2; j++)
            wmma::fill_fragment(acc[i][j], 0.0f);

    {
        __nv_bfloat16* s = stg[0];
        *(uint4*)(s + ar*BK + ac)      = *(const uint4*)(Ah0 + (size_t)ar*EE + ac);
        *(uint4*)(s + SA + ar*BK + ac) = *(const uint4*)(Al0 + (size_t)ar*EE + ac);
        const __nv_bfloat16* Bsrc = bsel ? Bl0 : Bh0;
        *(uint4*)(s + 2*SA + bsel*SB + br*BK + bc) = *(const uint4*)(Bsrc + (size_t)br*EE + bc);
    }
    __syncthreads();

    const int NS = EE / BK;
    for (int s = 0; s < NS; s++){
        const int buf = s & 1;
        uint4 rAh, rAl, rB;
        if (s+1 < NS){
            const int k0 = (s+1)*BK;
            rAh = *(const uint4*)(Ah0 + (size_t)ar*EE + k0 + ac);
            rAl = *(const uint4*)(Al0 + (size_t)ar*EE + k0 + ac);
            const __nv_bfloat16* Bsrc = bsel ? Bl0 : Bh0;
            rB  = *(const uint4*)(Bsrc + (size_t)br*EE + k0 + bc);
        }
        {
            __nv_bfloat16* sbuf = stg[buf];
            FragBc bh[2], bl[2];
            #pragma unroll
            for (int j = 0; j < 2; j++){
                wmma::load_matrix_sync(bh[j], sbuf + 2*SA      + (wn*32 + j*16)*BK, BK);
                wmma::load_matrix_sync(bl[j], sbuf + 2*SA + SB + (wn*32 + j*16)*BK, BK);
            }
            #pragma unroll
            for (int i = 0; i < 2; i++){
                FragA ah, al;
                wmma::load_matrix_sync(ah, sbuf      + (wm*32 + i*16)*BK, BK);
                wmma::load_matrix_sync(al, sbuf + SA + (wm*32 + i*16)*BK, BK);
                #pragma unroll
                for (int j = 0; j < 2; j++){ SPLIT_MMA(acc[i][j], ah, al, bh[j], bl[j]) }
            }
        }
        if (s+1 < NS){
            __nv_bfloat16* sn = stg[buf ^ 1];
            *(uint4*)(sn + ar*BK + ac)      = rAh;
            *(uint4*)(sn + SA + ar*BK + ac) = rAl;
            *(uint4*)(sn + 2*SA + bsel*SB + br*BK + bc) = rB;
        }
        __syncthreads();
    }

    float* C = (float*)sm_raw;
    #pragma unroll
    for (int i = 0; i < 2; i++)
        #pragma unroll
        for (int j = 0; j < 2; j++)
            wmma::store_matrix_sync(C + (wm*32 + i*16)*CLD + wn*32 + j*16,
                                    acc[i][j], CLD, wmma::mem_row_major);
    __syncthreads();
    for (int idx = tid; idx < BM*BN; idx += 256){
        int r = idx >> 6, c = idx & 63;
        int gi = i0 + r, gj = j0 + c;
        S[(size_t)gi*TT + gj] = (gj <= gi) ? C[r*CLD + c] : -INFINITY;
    }
}

// ---------------------------------------------------------------------------
// Softmax over QUERY axis, chunked 3-pass. Column j: valid rows i >= vs=j&~127
// (proven unchanged for 64-wide j tiles). P written as bf16 hi/lo ONLY for
// i >= vs (AV provably never reads i < vs).
// ---------------------------------------------------------------------------
__global__ void __launch_bounds__(256) sm_pass1()     // grid (TT/256, BB, NCH)
{
    const int b = blockIdx.y, z = blockIdx.z;
    const int j = blockIdx.x*256 + threadIdx.x;
    const float* S = g_S + (size_t)b*TT*TT;
    const int vs = j & ~127;
    const int r0 = max(z*CHR, vs), r1 = z*CHR + CHR;

    float m = -INFINITY;
    for (int i = r0; i < r1; i++)
        m = fmaxf(m, S[(size_t)i*TT + j]);
    float d = 0.0f;
    if (m != -INFINITY)
        for (int i = r0; i < r1; i++)
            d += __expf(S[(size_t)i*TT + j] - m);
    g_pm[b][z][j] = m;
    g_ps[b][z][j] = d;
}

__global__ void __launch_bounds__(256) sm_pass2()     // grid (TT/256, BB)
{
    const int b = blockIdx.y;
    const int j = blockIdx.x*256 + threadIdx.x;
    float m = -INFINITY;
    #pragma unroll
    for (int z = 0; z < NCH; z++) m = fmaxf(m, g_pm[b][z][j]);
    float d = 0.0f;
    #pragma unroll
    for (int z = 0; z < NCH; z++){
        float pm = g_pm[b][z][j];
        if (pm != -INFINITY) d += g_ps[b][z][j] * __expf(pm - m);
    }
    g_M[b][j] = m;
    g_R[b][j] = 1.0f / d;
}

__global__ void __launch_bounds__(256) sm_pass3()     // grid (TT/256, BB, NCH)
{
    const int b = blockIdx.y, z = blockIdx.z;
    const int j = blockIdx.x*256 + threadIdx.x;
    const float* S = g_S + (size_t)b*TT*TT;
    __nv_bfloat16* Ph = g_Phi + (size_t)b*TT*TT;
    __nv_bfloat16* Pl = g_Plo + (size_t)b*TT*TT;
    const int vs = j & ~127;
    const int r0 = max(z*CHR, vs), r1 = z*CHR + CHR;
    const float m = g_M[b][j];

    for (int i = r0; i < r1; i++){
        float e = __expf(S[(size_t)i*TT + j] - m);    // exp(-inf - m) = 0
        __nv_bfloat16 h, l; split2(e, h, l);
        Ph[(size_t)i*TT + j] = h;
        Pl[(size_t)i*TT + j] = l;
    }
}

// ---------------------------------------------------------------------------
// Fold 1/denom into V rows: VS[m,e] = (Vhi+Vlo)[m,e] * R[b][m%TT], hi/lo split
// ---------------------------------------------------------------------------
__global__ void __launch_bounds__(256) scale_v_kernel()
{
    size_t i = (size_t)blockIdx.x*blockDim.x + threadIdx.x;
    if (i >= (size_t)MT*EE) return;
    size_t m = i >> 10;                   // EE = 1024
    int b = (int)(m >> 11);               // TT = 2048
    int jrow = (int)(m & 2047);
    float v = (__bfloat162float(g_Vhi[i]) + __bfloat162float(g_Vlo[i])) * g_R[b][jrow];
    split2(v, g_VShi[i], g_VSlo[i]);
}

// ---------------------------------------------------------------------------
// Kernel: AV  out[b,i,e] = sum_j P[i,j] * VS[j,e]  (NN; B row-major k x n)
// Triangular k-limit: j < i0+BM. grid (EE/BN=16, TT/BM=16, BB)
// ---------------------------------------------------------------------------
__global__ void __launch_bounds__(256) av_wmma(float* __restrict__ out)
{
    __shared__ __align__(32) unsigned char sm_raw[SMEM_BYTES];

    const int b  = blockIdx.z;
    const int i0 = blockIdx.y * BM;
    const int e0 = blockIdx.x * BN;

    const __nv_bfloat16* Ah0 = g_Phi + (size_t)b*TT*TT + (size_t)i0*TT;
    const __nv_bfloat16* Al0 = g_Plo + (size_t)b*TT*TT + (size_t)i0*TT;
    const __nv_bfloat16* Bh0 = g_VShi + (size_t)b*TT*EE + e0;
    const __nv_bfloat16* Bl0 = g_VSlo + (size_t)b*TT*EE + e0;

    const int tid = threadIdx.x, wid = tid >> 5;
    const int wm = wid & 3, wn = wid >> 2;
    const int ar = tid >> 1, ac = (tid & 1) * 8;
    // B tile is BK x BN (16 x 64): row 0..15, col-group 0..7
    const int bt = tid & 127, br = bt >> 3, bc = (bt & 7) * 8;
    const int bsel = tid >> 7;

    __nv_bfloat16* stg[2];
    stg[0] = (__nv_bfloat16*)sm_raw;
    stg[1] = (__nv_bfloat16*)(sm_raw + STG_BYTES);

    FragC acc[2][2];
    #pragma unroll
    for (int i = 0; i < 2; i++)
        #pragma unroll
        for (int j = 0; j < 2; j++)
            wmma::fill_fragment(acc[i][j], 0.0f);

    {
        __nv_bfloat16* s = stg[0];
        *(uint4*)(s + ar*BK + ac)      = *(const uint4*)(Ah0 + (size_t)ar*TT + ac);
        *(uint4*)(s + SA + ar*BK + ac) = *(const uint4*)(Al0 + (size_t)ar*TT + ac);
        const __nv_bfloat16* Bsrc = bsel ? Bl0 : Bh0;
        *(uint4*)(s + 2*SA + bsel*SB + br*BN + bc) = *(const uint4*)(Bsrc + (size_t)br*EE + bc);
    }
    __syncthreads();

    const int NS = (i0 + BM) / BK;        // triangular limit
    for (int s = 0; s < NS; s++){
        const int buf = s & 1;
        uint4 rAh, rAl, rB;
        if (s+1 < NS){
            const int k0 = (s+1)*BK;
            rAh = *(const uint4*)(Ah0 + (size_t)ar*TT + k0 + ac);
            rAl = *(const uint4*)(Al0 + (size_t)ar*TT + k0 + ac);
            const __nv_bfloat16* Bsrc = bsel ? Bl0 : Bh0;
            rB  = *(const uint4*)(Bsrc + (size_t)(k0 + br)*EE + bc);
        }
        {
            __nv_bfloat16* sbuf = stg[buf];
            FragBr bh[2], bl[2];
            #pragma unroll
            for (int j = 0; j < 2; j++){
                wmma::load_matrix_sync(bh[j], sbuf + 2*SA      + (wn*32 + j*16), BN);
                wmma::load_matrix_sync(bl[j], sbuf + 2*SA + SB + (wn*32 + j*16), BN);
            }
            #pragma unroll
            for (int i = 0; i < 2; i++){
                FragA ah, al;
                wmma::load_matrix_sync(ah, sbuf      + (wm*32 + i*16)*BK, BK);
                wmma::load_matrix_sync(al, sbuf + SA + (wm*32 + i*16)*BK, BK);
                #pragma unroll
                for (int j = 0; j < 2; j++){ SPLIT_MMA(acc[i][j], ah, al, bh[j], bl[j]) }
            }
        }
        if (s+1 < NS){
            __nv_bfloat16* sn = stg[buf ^ 1];
            *(uint4*)(sn + ar*BK + ac)      = rAh;
            *(uint4*)(sn + SA + ar*BK + ac) = rAl;
            *(uint4*)(sn + 2*SA + bsel*SB + br*BN + bc) = rB;
        }
        __syncthreads();
    }

    // direct global store (fp32, ld = EE)
    #pragma unroll
    for (int i = 0; i < 2; i++)
        #pragma unroll
        for (int j = 0; j < 2; j++)
            wmma::store_matrix_sync(
                out + ((size_t)b*TT + i0 + wm*32 + i*16)*EE + e0 + wn*32 + j*16,
                acc[i][j], EE, wmma::mem_row_major);
}

// ---------------------------------------------------------------------------
// Inputs: 0=x_embeddings f32, 1=x i32 (unused), 2=Wk, 3=bk, 4=Wq, 5=bq,
//         6=Wv, 7=bv.  Output: (8,2048,1024) f32.
// ---------------------------------------------------------------------------
extern "C" void kernel_launch(void* const* d_in, const int* in_sizes, int n_in,
                              void* d_out, int out_size)
{
    (void)in_sizes; (void)n_in; (void)out_size;
    const float* X  = (const float*)d_in[0];
    const float* Wk = (const float*)d_in[2];
    const float* bk = (const float*)d_in[3];
    const float* Wq = (const float*)d_in[4];
    const float* bq = (const float*)d_in[5];
    const float* Wv = (const float*)d_in[6];
    const float* bv = (const float*)d_in[7];
    float* out = (float*)d_out;

    convert_all_kernel<<<2048, 256>>>(X, Wq, Wk, Wv);
    proj_wmma  <<<dim3(EE/BN, MT/BM, 3), 256>>>(bq, bk, bv);
    logits_wmma<<<dim3(TT/BN, TT/BM, BB), 256>>>();
    sm_pass1   <<<dim3(TT/256, BB, NCH), 256>>>();
    sm_pass2   <<<dim3(TT/256, BB), 256>>>();
    sm_pass3   <<<dim3(TT/256, BB, NCH), 256>>>();
    scale_v_kernel<<<(unsigned)(((size_t)MT*EE + 255)/256), 256>>>();
    av_wmma    <<<dim3(EE/BN, TT/BM, BB), 256>>>(out);
}

// round 11
// speedup vs baseline: 1.0803x; 1.0803x over previous
#include <cuda_runtime.h>
#include <cuda_bf16.h>
#include <mma.h>
#include <math.h>
#include <stdint.h>

using namespace nvcuda;

#define BB 8
#define TT 2048
#define EE 1024
#define MT (BB*TT)   // 16384
#define NCH 8
#define CHR (TT/NCH)

#define BM 128
#define BN 64
#define BK 16
// padded smem strides (conflict-free ldmatrix phases; all multiples of 8)
#define ASTR 24                    // A tile row stride (elements)
#define BSTR 24                    // B NT tile row stride
#define BAVSTR 72                  // AV B tile row stride (16 x 64 tile)
#define APAD (BM*ASTR)             // 3072 el
#define BPAD (BN*BSTR)             // 1536 el
#define BPAV (BK*BAVSTR)           // 1152 el
#define CLD 72                     // C tile ld (fp32), padded
#define SMEM_BYTES 36864           // max(2*(2*APAD+2*BPAD)*2 = 36864, 128*72*4)

// ---------------- device-global scratch -------------------------------------
__device__ __nv_bfloat16 g_Xhi[(size_t)MT*EE],  g_Xlo[(size_t)MT*EE];
__device__ __nv_bfloat16 g_Whi[3][(size_t)EE*EE], g_Wlo[3][(size_t)EE*EE];
__device__ __nv_bfloat16 g_Qhi[(size_t)MT*EE],  g_Qlo[(size_t)MT*EE];
__device__ __nv_bfloat16 g_Khi[(size_t)MT*EE],  g_Klo[(size_t)MT*EE];
__device__ __nv_bfloat16 g_Vhi[(size_t)MT*EE],  g_Vlo[(size_t)MT*EE];
__device__ __nv_bfloat16 g_VShi[(size_t)MT*EE], g_VSlo[(size_t)MT*EE];  // V * 1/denom
__device__ float         g_S[(size_t)BB*TT*TT];
__device__ __nv_bfloat16 g_Phi[(size_t)BB*TT*TT], g_Plo[(size_t)BB*TT*TT];
__device__ float         g_pm[BB][NCH][TT], g_ps[BB][NCH][TT];

__device__ __forceinline__ void split2(float v, __nv_bfloat16& h, __nv_bfloat16& l){
    h = __float2bfloat16(v);
    l = __float2bfloat16(v - __bfloat162float(h));
}

// ---------------------------------------------------------------------------
// preconvert fp32 -> bf16 hi/lo (X + Wq + Wk + Wv in one grid-stride launch)
// ---------------------------------------------------------------------------
__global__ void convert_all_kernel(const float* __restrict__ X,
                                   const float* __restrict__ Wq,
                                   const float* __restrict__ Wk,
                                   const float* __restrict__ Wv)
{
    const size_t nX = (size_t)MT*EE, nW = (size_t)EE*EE;
    const size_t total = nX + 3*nW;
    for (size_t i = (size_t)blockIdx.x*blockDim.x + threadIdx.x;
         i < total; i += (size_t)gridDim.x*blockDim.x){
        if (i < nX)             { split2(X[i],  g_Xhi[i],  g_Xlo[i]); }
        else if (i < nX + nW)   { size_t k=i-nX;      split2(Wq[k], g_Whi[0][k], g_Wlo[0][k]); }
        else if (i < nX + 2*nW) { size_t k=i-nX-nW;   split2(Wk[k], g_Whi[1][k], g_Wlo[1][k]); }
        else                    { size_t k=i-nX-2*nW; split2(Wv[k], g_Whi[2][k], g_Wlo[2][k]); }
    }
}

// ---------------------------------------------------------------------------
// WMMA fragment typedefs
// ---------------------------------------------------------------------------
typedef wmma::fragment<wmma::matrix_a, 16,16,16, __nv_bfloat16, wmma::row_major> FragA;
typedef wmma::fragment<wmma::matrix_b, 16,16,16, __nv_bfloat16, wmma::col_major> FragBc;
typedef wmma::fragment<wmma::matrix_b, 16,16,16, __nv_bfloat16, wmma::row_major> FragBr;
typedef wmma::fragment<wmma::accumulator, 16,16,16, float> FragC;

// 3-MMA split accumulate: acc += Ah*Bh + Ah*Bl + Al*Bh
#define SPLIT_MMA(acc, ah, al, bh, bl)            \
    wmma::mma_sync(acc, ah, bh, acc);             \
    wmma::mma_sync(acc, ah, bl, acc);             \
    wmma::mma_sync(acc, al, bh, acc);

// ---------------------------------------------------------------------------
// Kernel: QKV projection  C[m,n] = sum_e X[m,e]*W[n,e] + b[n]  (NT)
// grid (EE/BN=16, MT/BM=128, 3), 256 threads
// ---------------------------------------------------------------------------
__global__ void __launch_bounds__(256) proj_wmma(
    const float* __restrict__ bq, const float* __restrict__ bk, const float* __restrict__ bv)
{
    __shared__ __align__(32) unsigned char sm_raw[SMEM_BYTES];

    const int z  = blockIdx.z;
    const int m0 = blockIdx.y * BM;
    const int n0 = blockIdx.x * BN;
    const __nv_bfloat16* Wh = g_Whi[z];
    const __nv_bfloat16* Wl = g_Wlo[z];
    const float* bias = (z==0)? bq : (z==1)? bk : bv;
    __nv_bfloat16* Ohi = (z==0)? g_Qhi : (z==1)? g_Khi : g_Vhi;
    __nv_bfloat16* Olo = (z==0)? g_Qlo : (z==1)? g_Klo : g_Vlo;

    const int tid = threadIdx.x, wid = tid >> 5;
    const int wm = wid & 3, wn = wid >> 2;           // 4 x 2 warp grid
    const int ar = tid >> 1, ac = (tid & 1) * 8;
    const int bt = tid & 127, br = bt >> 1, bc = (bt & 1) * 8;
    const int bsel = tid >> 7;                        // 0: hi, 1: lo

    const int STG_EL = 2*APAD + 2*BPAD;              // elements per stage
    __nv_bfloat16* stg[2];
    stg[0] = (__nv_bfloat16*)sm_raw;
    stg[1] = stg[0] + STG_EL;

    FragC acc[2][2];
    #pragma unroll
    for (int i = 0; i < 2; i++)
        #pragma unroll
        for (int j = 0; j < 2; j++)
            wmma::fill_fragment(acc[i][j], 0.0f);

    {
        __nv_bfloat16* s = stg[0];
        *(uint4*)(s + ar*ASTR + ac)        = *(const uint4*)(g_Xhi + (size_t)(m0+ar)*EE + ac);
        *(uint4*)(s + APAD + ar*ASTR + ac) = *(const uint4*)(g_Xlo + (size_t)(m0+ar)*EE + ac);
        const __nv_bfloat16* Wsrc = bsel ? Wl : Wh;
        *(uint4*)(s + 2*APAD + bsel*BPAD + br*BSTR + bc) = *(const uint4*)(Wsrc + (size_t)(n0+br)*EE + bc);
    }
    __syncthreads();

    const int NS = EE / BK;
    for (int s = 0; s < NS; s++){
        const int buf = s & 1;
        uint4 rAh, rAl, rB;
        if (s+1 < NS){
            const int k0 = (s+1)*BK;
            rAh = *(const uint4*)(g_Xhi + (size_t)(m0+ar)*EE + k0 + ac);
            rAl = *(const uint4*)(g_Xlo + (size_t)(m0+ar)*EE + k0 + ac);
            const __nv_bfloat16* Wsrc = bsel ? Wl : Wh;
            rB  = *(const uint4*)(Wsrc + (size_t)(n0+br)*EE + k0 + bc);
        }
        {
            __nv_bfloat16* sbuf = stg[buf];
            FragBc bh[2], bl[2];
            #pragma unroll
            for (int j = 0; j < 2; j++){
                wmma::load_matrix_sync(bh[j], sbuf + 2*APAD        + (wn*32 + j*16)*BSTR, BSTR);
                wmma::load_matrix_sync(bl[j], sbuf + 2*APAD + BPAD + (wn*32 + j*16)*BSTR, BSTR);
            }
            #pragma unroll
            for (int i = 0; i < 2; i++){
                FragA ah, al;
                wmma::load_matrix_sync(ah, sbuf        + (wm*32 + i*16)*ASTR, ASTR);
                wmma::load_matrix_sync(al, sbuf + APAD + (wm*32 + i*16)*ASTR, ASTR);
                #pragma unroll
                for (int j = 0; j < 2; j++){ SPLIT_MMA(acc[i][j], ah, al, bh[j], bl[j]) }
            }
        }
        if (s+1 < NS){
            __nv_bfloat16* sn = stg[buf ^ 1];
            *(uint4*)(sn + ar*ASTR + ac)        = rAh;
            *(uint4*)(sn + APAD + ar*ASTR + ac) = rAl;
            *(uint4*)(sn + 2*APAD + bsel*BPAD + br*BSTR + bc) = rB;
        }
        __syncthreads();
    }

    float* C = (float*)sm_raw;
    #pragma unroll
    for (int i = 0; i < 2; i++)
        #pragma unroll
        for (int j = 0; j < 2; j++)
            wmma::store_matrix_sync(C + (wm*32 + i*16)*CLD + wn*32 + j*16,
                                    acc[i][j], CLD, wmma::mem_row_major);
    __syncthreads();
    for (int idx = tid; idx < BM*BN; idx += 256){
        int r = idx >> 6, c = idx & 63;
        float v = C[r*CLD + c] + bias[n0 + c];
        __nv_bfloat16 h, l; split2(v, h, l);
        Ohi[(size_t)(m0+r)*EE + n0 + c] = h;
        Olo[(size_t)(m0+r)*EE + n0 + c] = l;
    }
}

// ---------------------------------------------------------------------------
// Kernel: masked logits S[b,i,j] = Q.K (NT); j>i -> -inf; tiles with
// j0 >= i0+BM skipped. grid (TT/BN=32 (j), TT/BM=16 (i), BB)
// ---------------------------------------------------------------------------
__global__ void __launch_bounds__(256) logits_wmma()
{
    const int b  = blockIdx.z;
    const int i0 = blockIdx.y * BM;
    const int j0 = blockIdx.x * BN;
    if (j0 >= i0 + BM) return;

    __shared__ __align__(32) unsigned char sm_raw[SMEM_BYTES];

    const __nv_bfloat16* Ah0 = g_Qhi + (size_t)(b*TT + i0)*EE;
    const __nv_bfloat16* Al0 = g_Qlo + (size_t)(b*TT + i0)*EE;
    const __nv_bfloat16* Bh0 = g_Khi + (size_t)(b*TT + j0)*EE;
    const __nv_bfloat16* Bl0 = g_Klo + (size_t)(b*TT + j0)*EE;
    float* S = g_S + (size_t)b*TT*TT;

    const int tid = threadIdx.x, wid = tid >> 5;
    const int wm = wid & 3, wn = wid >> 2;
    const int ar = tid >> 1, ac = (tid & 1) * 8;
    const int bt = tid & 127, br = bt >> 1, bc = (bt & 1) * 8;
    const int bsel = tid >> 7;

    const int STG_EL = 2*APAD + 2*BPAD;
    __nv_bfloat16* stg[2];
    stg[0] = (__nv_bfloat16*)sm_raw;
    stg[1] = stg[0] + STG_EL;

    FragC acc[2][2];
    #pragma unroll
    for (int i = 0; i < 2; i++)
        #pragma unroll
        for (int j = 0; j < 2; j++)
            wmma::fill_fragment(acc[i][j], 0.0f);

    {
        __nv_bfloat16* s = stg[0];
        *(uint4*)(s + ar*ASTR + ac)        = *(const uint4*)(Ah0 + (size_t)ar*EE + ac);
        *(uint4*)(s + APAD + ar*ASTR + ac) = *(const uint4*)(Al0 + (size_t)ar*EE + ac);
        const __nv_bfloat16* Bsrc = bsel ? Bl0 : Bh0;
        *(uint4*)(s + 2*APAD + bsel*BPAD + br*BSTR + bc) = *(const uint4*)(Bsrc + (size_t)br*EE + bc);
    }
    __syncthreads();

    const int NS = EE / BK;
    for (int s = 0; s < NS; s++){
        const int buf = s & 1;
        uint4 rAh, rAl, rB;
        if (s+1 < NS){
            const int k0 = (s+1)*BK;
            rAh = *(const uint4*)(Ah0 + (size_t)ar*EE + k0 + ac);
            rAl = *(const uint4*)(Al0 + (size_t)ar*EE + k0 + ac);
            const __nv_bfloat16* Bsrc = bsel ? Bl0 : Bh0;
            rB  = *(const uint4*)(Bsrc + (size_t)br*EE + k0 + bc);
        }
        {
            __nv_bfloat16* sbuf = stg[buf];
            FragBc bh[2], bl[2];
            #pragma unroll
            for (int j = 0; j < 2; j++){
                wmma::load_matrix_sync(bh[j], sbuf + 2*APAD        + (wn*32 + j*16)*BSTR, BSTR);
                wmma::load_matrix_sync(bl[j], sbuf + 2*APAD + BPAD + (wn*32 + j*16)*BSTR, BSTR);
            }
            #pragma unroll
            for (int i = 0; i < 2; i++){
                FragA ah, al;
                wmma::load_matrix_sync(ah, sbuf        + (wm*32 + i*16)*ASTR, ASTR);
                wmma::load_matrix_sync(al, sbuf + APAD + (wm*32 + i*16)*ASTR, ASTR);
                #pragma unroll
                for (int j = 0; j < 2; j++){ SPLIT_MMA(acc[i][j], ah, al, bh[j], bl[j]) }
            }
        }
        if (s+1 < NS){
            __nv_bfloat16* sn = stg[buf ^ 1];
            *(uint4*)(sn + ar*ASTR + ac)        = rAh;
            *(uint4*)(sn + APAD + ar*ASTR + ac) = rAl;
            *(uint4*)(sn + 2*APAD + bsel*BPAD + br*BSTR + bc) = rB;
        }
        __syncthreads();
    }

    float* C = (float*)sm_raw;
    #pragma unroll
    for (int i = 0; i < 2; i++)
        #pragma unroll
        for (int j = 0; j < 2; j++)
            wmma::store_matrix_sync(C + (wm*32 + i*16)*CLD + wn*32 + j*16,
                                    acc[i][j], CLD, wmma::mem_row_major);
    __syncthreads();
    for (int idx = tid; idx < BM*BN; idx += 256){
        int r = idx >> 6, c = idx & 63;
        int gi = i0 + r, gj = j0 + c;
        S[(size_t)gi*TT + gj] = (gj <= gi) ? C[r*CLD + c] : -INFINITY;
    }
}

// ---------------------------------------------------------------------------
// sm_pass1: per-chunk column max + expsum. grid (TT/256, BB, NCH)
// ---------------------------------------------------------------------------
__global__ void __launch_bounds__(256) sm_pass1()
{
    const int b = blockIdx.y, z = blockIdx.z;
    const int j = blockIdx.x*256 + threadIdx.x;
    const float* S = g_S + (size_t)b*TT*TT;
    const int vs = j & ~127;
    const int r0 = max(z*CHR, vs), r1 = z*CHR + CHR;

    float m = -INFINITY;
    for (int i = r0; i < r1; i++)
        m = fmaxf(m, S[(size_t)i*TT + j]);
    float d = 0.0f;
    if (m != -INFINITY)
        for (int i = r0; i < r1; i++)
            d += __expf(S[(size_t)i*TT + j] - m);
    g_pm[b][z][j] = m;
    g_ps[b][z][j] = d;
}

// ---------------------------------------------------------------------------
// sm23v: fused combine + P-write (chunk) + V-scale (z==0 blocks only).
// grid (TT/256, BB, NCH). Each block recombines partials for its 256 cols
// (8 reads/col), writes P = exp(s-m) bf16 hi/lo for its row chunk; z==0
// blocks additionally scale their 256 V rows by 1/denom into VS.
// ---------------------------------------------------------------------------
__global__ void __launch_bounds__(256) sm23v()
{
    __shared__ float rs[256];
    const int b = blockIdx.y, z = blockIdx.z;
    const int tx = threadIdx.x;
    const int j = blockIdx.x*256 + tx;

    // combine (deterministic, identical in every block)
    float m = -INFINITY;
    #pragma unroll
    for (int z2 = 0; z2 < NCH; z2++) m = fmaxf(m, g_pm[b][z2][j]);
    float d = 0.0f;
    #pragma unroll
    for (int z2 = 0; z2 < NCH; z2++){
        float pm = g_pm[b][z2][j];
        if (pm != -INFINITY) d += g_ps[b][z2][j] * __expf(pm - m);
    }
    const float r = 1.0f / d;

    // P write for this chunk
    const float* S = g_S + (size_t)b*TT*TT;
    __nv_bfloat16* Ph = g_Phi + (size_t)b*TT*TT;
    __nv_bfloat16* Pl = g_Plo + (size_t)b*TT*TT;
    const int vs = j & ~127;
    const int r0 = max(z*CHR, vs), r1 = z*CHR + CHR;
    for (int i = r0; i < r1; i++){
        float e = __expf(S[(size_t)i*TT + j] - m);    // exp(-inf - m) = 0
        __nv_bfloat16 h, l; split2(e, h, l);
        Ph[(size_t)i*TT + j] = h;
        Pl[(size_t)i*TT + j] = l;
    }

    // V scaling: z==0 blocks handle their 256 rows (row index == column index j)
    if (z == 0){
        rs[tx] = r;
        __syncthreads();
        const int j0 = blockIdx.x*256;
        for (int rr = 0; rr < 256; rr++){
            const float rv = rs[rr];
            const size_t base = ((size_t)b*TT + j0 + rr)*EE;
            for (int e = tx; e < EE; e += 256){
                float v = (__bfloat162float(g_Vhi[base+e]) +
                           __bfloat162float(g_Vlo[base+e])) * rv;
                split2(v, g_VShi[base+e], g_VSlo[base+e]);
            }
        }
    }
}

// ---------------------------------------------------------------------------
// Kernel: AV  out[b,i,e] = sum_j P[i,j] * VS[j,e]  (NN; B row-major k x n)
// Triangular k-limit: j < i0+BM. grid (EE/BN=16, TT/BM=16, BB)
// ---------------------------------------------------------------------------
__global__ void __launch_bounds__(256) av_wmma(float* __restrict__ out)
{
    __shared__ __align__(32) unsigned char sm_raw[SMEM_BYTES];

    const int b  = blockIdx.z;
    const int i0 = blockIdx.y * BM;
    const int e0 = blockIdx.x * BN;

    const __nv_bfloat16* Ah0 = g_Phi + (size_t)b*TT*TT + (size_t)i0*TT;
    const __nv_bfloat16* Al0 = g_Plo + (size_t)b*TT*TT + (size_t)i0*TT;
    const __nv_bfloat16* Bh0 = g_VShi + (size_t)b*TT*EE + e0;
    const __nv_bfloat16* Bl0 = g_VSlo + (size_t)b*TT*EE + e0;

    const int tid = threadIdx.x, wid = tid >> 5;
    const int wm = wid & 3, wn = wid >> 2;
    const int ar = tid >> 1, ac = (tid & 1) * 8;
    const int bt = tid & 127, br = bt >> 3, bc = (bt & 7) * 8;
    const int bsel = tid >> 7;

    const int STG_EL = 2*APAD + 2*BPAV;
    __nv_bfloat16* stg[2];
    stg[0] = (__nv_bfloat16*)sm_raw;
    stg[1] = stg[0] + STG_EL;

    FragC acc[2][2];
    #pragma unroll
    for (int i = 0; i < 2; i++)
        #pragma unroll
        for (int j = 0; j < 2; j++)
            wmma::fill_fragment(acc[i][j], 0.0f);

    {
        __nv_bfloat16* s = stg[0];
        *(uint4*)(s + ar*ASTR + ac)        = *(const uint4*)(Ah0 + (size_t)ar*TT + ac);
        *(uint4*)(s + APAD + ar*ASTR + ac) = *(const uint4*)(Al0 + (size_t)ar*TT + ac);
        const __nv_bfloat16* Bsrc = bsel ? Bl0 : Bh0;
        *(uint4*)(s + 2*APAD + bsel*BPAV + br*BAVSTR + bc) = *(const uint4*)(Bsrc + (size_t)br*EE + bc);
    }
    __syncthreads();

    const int NS = (i0 + BM) / BK;        // triangular limit
    for (int s = 0; s < NS; s++){
        const int buf = s & 1;
        uint4 rAh, rAl, rB;
        if (s+1 < NS){
            const int k0 = (s+1)*BK;
            rAh = *(const uint4*)(Ah0 + (size_t)ar*TT + k0 + ac);
            rAl = *(const uint4*)(Al0 + (size_t)ar*TT + k0 + ac);
            const __nv_bfloat16* Bsrc = bsel ? Bl0 : Bh0;
            rB  = *(const uint4*)(Bsrc + (size_t)(k0 + br)*EE + bc);
        }
        {
            __nv_bfloat16* sbuf = stg[buf];
            FragBr bh[2], bl[2];
            #pragma unroll
            for (int j = 0; j < 2; j++){
                wmma::load_matrix_sync(bh[j], sbuf + 2*APAD        + (wn*32 + j*16), BAVSTR);
                wmma::load_matrix_sync(bl[j], sbuf + 2*APAD + BPAV + (wn*32 + j*16), BAVSTR);
            }
            #pragma unroll
            for (int i = 0; i < 2; i++){
                FragA ah, al;
                wmma::load_matrix_sync(ah, sbuf        + (wm*32 + i*16)*ASTR, ASTR);
                wmma::load_matrix_sync(al, sbuf + APAD + (wm*32 + i*16)*ASTR, ASTR);
                #pragma unroll
                for (int j = 0; j < 2; j++){ SPLIT_MMA(acc[i][j], ah, al, bh[j], bl[j]) }
            }
        }
        if (s+1 < NS){
            __nv_bfloat16* sn = stg[buf ^ 1];
            *(uint4*)(sn + ar*ASTR + ac)        = rAh;
            *(uint4*)(sn + APAD + ar*ASTR + ac) = rAl;
            *(uint4*)(sn + 2*APAD + bsel*BPAV + br*BAVSTR + bc) = rB;
        }
        __syncthreads();
    }

    #pragma unroll
    for (int i = 0; i < 2; i++)
        #pragma unroll
        for (int j = 0; j < 2; j++)
            wmma::store_matrix_sync(
                out + ((size_t)b*TT + i0 + wm*32 + i*16)*EE + e0 + wn*32 + j*16,
                acc[i][j], EE, wmma::mem_row_major);
}

// ---------------------------------------------------------------------------
// Inputs: 0=x_embeddings f32, 1=x i32 (unused), 2=Wk, 3=bk, 4=Wq, 5=bq,
//         6=Wv, 7=bv.  Output: (8,2048,1024) f32.
// ---------------------------------------------------------------------------
extern "C" void kernel_launch(void* const* d_in, const int* in_sizes, int n_in,
                              void* d_out, int out_size)
{
    (void)in_sizes; (void)n_in; (void)out_size;
    const float* X  = (const float*)d_in[0];
    const float* Wk = (const float*)d_in[2];
    const float* bk = (const float*)d_in[3];
    const float* Wq = (const float*)d_in[4];
    const float* bq = (const float*)d_in[5];
    const float* Wv = (const float*)d_in[6];
    const float* bv = (const float*)d_in[7];
    float* out = (float*)d_out;

    convert_all_kernel<<<2048, 256>>>(X, Wq, Wk, Wv);          // launch 0
    proj_wmma  <<<dim3(EE/BN, MT/BM, 3), 256>>>(bq, bk, bv);   // launch 1
    logits_wmma<<<dim3(TT/BN, TT/BM, BB), 256>>>();            // launch 2
    sm_pass1   <<<dim3(TT/256, BB, NCH), 256>>>();             // launch 3
    sm23v      <<<dim3(TT/256, BB, NCH), 256>>>();             // launch 4
    av_wmma    <<<dim3(EE/BN, TT/BM, BB), 256>>>(out);         // launch 5
}